// round 13
// baseline (speedup 1.0000x reference)
#include <cuda_runtime.h>
#include <cuda_fp16.h>
#include <cstdint>
#include <math.h>

#define BATCH   16384
#define IN_DIM  1024
#define NE      6
#define ND      20
#define H1D     256
#define H2D     128
#define EOUT    10
#define GHID    64
#define THID    64

// ---- scratch (device globals; no allocations allowed) ----
__device__ __half g_xh[BATCH * IN_DIM];        // fp16, k-permuted per 32-chunk (32 MB)
__device__ __half g_w1h[NE * H1D * IN_DIM];    // fp16, [e][n][k-perm]          (3 MB)
__device__ __half g_w2h[NE * H2D * H1D];       // fp16, [e][n][k-perm]          (384 KB)
__device__ __half g_gw1h[ND * GHID * IN_DIM];  // fp16, [d][n][k-perm]          (2.6 MB)
__device__ __half g_h1h[BATCH * NE * H1D];     // fp16, [m][e*256 + perm]       (50 MB)
__device__ float  g_eo[BATCH * NE * EOUT];     // fp32 [b][e][o]                (3.9 MB)
__device__ int    g_cnt[ND];
__device__ int    g_idx[ND * BATCH];

// ================= helpers =================
__device__ __forceinline__ uint32_t h2_as_u32(__half2 h) {
    return *(uint32_t*)&h;
}
__device__ __host__ __forceinline__ int perm16(int k) {
    return ((k & 7) >> 1) * 8 + (k >> 3) * 2 + (k & 1);
}
__device__ __forceinline__ void mma16(float* c,
                                      uint32_t a0, uint32_t a1, uint32_t a2, uint32_t a3,
                                      uint32_t b0, uint32_t b1) {
    asm volatile(
        "mma.sync.aligned.m16n8k16.row.col.f32.f16.f16.f32 "
        "{%0,%1,%2,%3}, {%4,%5,%6,%7}, {%8,%9}, {%0,%1,%2,%3};"
        : "+f"(c[0]), "+f"(c[1]), "+f"(c[2]), "+f"(c[3])
        : "r"(a0), "r"(a1), "r"(a2), "r"(a3), "r"(b0), "r"(b1));
}

// ================= prep: X -> fp16, k-permuted + zero counters =================
__global__ void x_prep_kernel(const float* __restrict__ X) {
    if (blockIdx.x == 0 && threadIdx.x < ND) g_cnt[threadIdx.x] = 0;
    int idx = blockIdx.x * 256 + threadIdx.x;
    int m = idx >> 7;
    int rest = idx & 127;
    int c = rest >> 2, t = rest & 3;
    const float* src = X + (size_t)m * IN_DIM + c * 32 + 2 * t;
    float2 v0 = *(const float2*)(src + 0);
    float2 v1 = *(const float2*)(src + 8);
    float2 v2 = *(const float2*)(src + 16);
    float2 v3 = *(const float2*)(src + 24);
    uint4 o;
    o.x = h2_as_u32(__floats2half2_rn(v0.x, v0.y));
    o.y = h2_as_u32(__floats2half2_rn(v1.x, v1.y));
    o.z = h2_as_u32(__floats2half2_rn(v2.x, v2.y));
    o.w = h2_as_u32(__floats2half2_rn(v3.x, v3.y));
    *(uint4*)(g_xh + (size_t)m * IN_DIM + c * 32 + t * 8) = o;
}

// ================= bucketing =================
__global__ void bucket_kernel(const int* __restrict__ dom) {
    int b = blockIdx.x * blockDim.x + threadIdx.x;
    if (b < BATCH) {
        int d = dom[b];
        int p = atomicAdd(&g_cnt[d], 1);
        g_idx[d * BATCH + p] = b;
    }
}

// ================= merged weight prep =================
__device__ __forceinline__ void w_prep_tile(const float* __restrict__ W,
                                            __half* __restrict__ WT,
                                            int K, int N, int e, int kbi, int nbi,
                                            float (*tile)[33])
{
    int k0 = kbi * 32, n0 = nbi * 32;
    const float* Wp = W + (size_t)e * K * N;
    __half* Tp = WT + (size_t)e * N * K;
    int tx = threadIdx.x, ty = threadIdx.y;
#pragma unroll
    for (int j = 0; j < 32; j += 8)
        tile[ty + j][tx] = Wp[(size_t)(k0 + ty + j) * N + n0 + tx];
    __syncthreads();
#pragma unroll
    for (int j = 0; j < 32; j += 8)
        Tp[(size_t)(n0 + ty + j) * K + k0 + perm16(tx)] = __float2half_rn(tile[tx][ty + j]);
}

__global__ void w_prep_all_kernel(const float* __restrict__ Ew1,
                                  const float* __restrict__ Ew2,
                                  const float* __restrict__ Gw1,
                                  __half* __restrict__ w1h,
                                  __half* __restrict__ w2h,
                                  __half* __restrict__ gw1h)
{
    __shared__ float tile[32][33];
    int b = blockIdx.x;
    if (b < 1536) {
        int e = b >> 8, r = b & 255;
        w_prep_tile(Ew1, w1h, IN_DIM, H1D, e, r & 31, r >> 5, tile);
    } else if (b < 1728) {
        int bb = b - 1536;
        int e = bb >> 5, r = bb & 31;
        w_prep_tile(Ew2, w2h, H1D, H2D, e, r & 7, r >> 3, tile);
    } else {
        int bb = b - 1728;
        int d = bb >> 6, r = bb & 63;
        w_prep_tile(Gw1, gw1h, IN_DIM, GHID, d, r & 31, r >> 5, tile);
    }
}

// ================= expert L1: 256x128 CTA tile, warp 64x64, direct LDG =========
// grid (64, 2, 6)
__global__ __launch_bounds__(256, 1)
void expert_l1_mma(const float* __restrict__ bias)
{
    const int tid = threadIdx.x, lane = tid & 31, wid = tid >> 5;
    const int gid = lane >> 2, tig = lane & 3;
    const int warpM = wid & 3, warpN = wid >> 2;
    const int m0 = blockIdx.x * 256;
    const int n0 = blockIdx.y * 128;
    const int e  = blockIdx.z;

    const __half* Ap = g_xh + (size_t)(m0 + warpM * 64 + gid) * IN_DIM + tig * 8;
    const __half* Bp = g_w1h + (size_t)(e * H1D + n0 + warpN * 64 + gid) * IN_DIM + tig * 8;

    float acc[4][8][4];
#pragma unroll
    for (int mt = 0; mt < 4; mt++)
#pragma unroll
        for (int nt = 0; nt < 8; nt++)
#pragma unroll
            for (int q = 0; q < 4; q++) acc[mt][nt][q] = 0.f;

#pragma unroll 2
    for (int c = 0; c < IN_DIM / 32; c++) {
        const __half* Ac = Ap + c * 32;
        const __half* Bc = Bp + c * 32;
        uint4 Ar[4][2];
#pragma unroll
        for (int mt = 0; mt < 4; mt++)
#pragma unroll
            for (int rr = 0; rr < 2; rr++)
                Ar[mt][rr] = *(const uint4*)(Ac + (mt * 16 + rr * 8) * IN_DIM);
#pragma unroll
        for (int nt = 0; nt < 8; nt++) {
            uint4 Br = *(const uint4*)(Bc + nt * 8 * IN_DIM);
#pragma unroll
            for (int mt = 0; mt < 4; mt++) {
                mma16(acc[mt][nt], Ar[mt][0].x, Ar[mt][1].x, Ar[mt][0].y, Ar[mt][1].y, Br.x, Br.y);
                mma16(acc[mt][nt], Ar[mt][0].z, Ar[mt][1].z, Ar[mt][0].w, Ar[mt][1].w, Br.z, Br.w);
            }
        }
    }

    // epilogue: bias + relu -> fp16 permuted; STG.128 per (mt,rr,cc)
#pragma unroll
    for (int mt = 0; mt < 4; mt++)
#pragma unroll
        for (int rr = 0; rr < 2; rr++) {
            int row = m0 + warpM * 64 + mt * 16 + rr * 8 + gid;
#pragma unroll
            for (int cc = 0; cc < 2; cc++) {
                uint32_t v[4];
#pragma unroll
                for (int q = 0; q < 4; q++) {
                    int nt = cc * 4 + q;
                    int nn = n0 + warpN * 64 + nt * 8 + tig * 2;
                    float b0 = bias[e * H1D + nn];
                    float b1 = bias[e * H1D + nn + 1];
                    v[q] = h2_as_u32(__floats2half2_rn(
                        fmaxf(acc[mt][nt][rr * 2 + 0] + b0, 0.f),
                        fmaxf(acc[mt][nt][rr * 2 + 1] + b1, 0.f)));
                }
                char* dst = (char*)g_h1h + (size_t)row * (NE * H1D * 2) + e * (H1D * 2)
                          + (size_t)(n0 / 32 + warpN * 2 + cc) * 64 + tig * 16;
                *(uint4*)dst = make_uint4(v[0], v[1], v[2], v[3]);
            }
        }
}

// ================= expert L2 (+fused L3): unchanged from R12 =================
#define CS_PITCH 132
__global__ __launch_bounds__(256, 2)
void expert_l2_mma(const float* __restrict__ b2, const float* __restrict__ W3,
                   const float* __restrict__ b3)
{
    extern __shared__ uint32_t sm[];
    float* Cs   = (float*)sm;
    float* sW3  = (float*)((char*)sm + 128 * CS_PITCH * 4);
    float* sEb3 = sW3 + H2D * EOUT;

    const int tid = threadIdx.x, lane = tid & 31, wid = tid >> 5;
    const int gid = lane >> 2, tig = lane & 3;
    const int warpM = wid & 3, warpN = wid >> 2;
    const int m0 = blockIdx.x * 128;
    const int e  = blockIdx.z;

    for (int i = tid; i < H2D * EOUT; i += 256) sW3[i] = W3[e * H2D * EOUT + i];
    if (tid < EOUT) sEb3[tid] = b3[e * EOUT + tid];

    const __half* Ap = g_h1h + (size_t)(m0 + warpM * 32 + gid) * (NE * H1D) + e * H1D + tig * 8;
    const __half* Bp = g_w2h + (size_t)(e * H2D + warpN * 64 + gid) * H1D + tig * 8;

    float acc[2][8][4];
#pragma unroll
    for (int mt = 0; mt < 2; mt++)
#pragma unroll
        for (int nt = 0; nt < 8; nt++)
#pragma unroll
            for (int q = 0; q < 4; q++) acc[mt][nt][q] = 0.f;

#pragma unroll
    for (int c = 0; c < H1D / 32; c++) {
        const __half* Ac = Ap + c * 32;
        const __half* Bc = Bp + c * 32;
        uint4 Ar[2][2];
#pragma unroll
        for (int mt = 0; mt < 2; mt++)
#pragma unroll
            for (int rr = 0; rr < 2; rr++)
                Ar[mt][rr] = *(const uint4*)(Ac + (mt * 16 + rr * 8) * (NE * H1D));
#pragma unroll
        for (int nt = 0; nt < 8; nt++) {
            uint4 Br = *(const uint4*)(Bc + nt * 8 * H1D);
#pragma unroll
            for (int mt = 0; mt < 2; mt++) {
                mma16(acc[mt][nt], Ar[mt][0].x, Ar[mt][1].x, Ar[mt][0].y, Ar[mt][1].y, Br.x, Br.y);
                mma16(acc[mt][nt], Ar[mt][0].z, Ar[mt][1].z, Ar[mt][0].w, Ar[mt][1].w, Br.z, Br.w);
            }
        }
    }

    __syncthreads();
#pragma unroll
    for (int mt = 0; mt < 2; mt++) {
        int r = warpM * 32 + mt * 16 + gid;
#pragma unroll
        for (int nt = 0; nt < 8; nt++) {
            int cc = warpN * 64 + nt * 8 + tig * 2;
            float bb0 = b2[e * H2D + cc];
            float bb1 = b2[e * H2D + cc + 1];
            Cs[r * CS_PITCH + cc]           = fmaxf(acc[mt][nt][0] + bb0, 0.f);
            Cs[r * CS_PITCH + cc + 1]       = fmaxf(acc[mt][nt][1] + bb1, 0.f);
            Cs[(r + 8) * CS_PITCH + cc]     = fmaxf(acc[mt][nt][2] + bb0, 0.f);
            Cs[(r + 8) * CS_PITCH + cc + 1] = fmaxf(acc[mt][nt][3] + bb1, 0.f);
        }
    }
    __syncthreads();

    for (int rr = 0; rr < 16; rr++) {
        int row = wid * 16 + rr;
        float p[EOUT];
#pragma unroll
        for (int o = 0; o < EOUT; o++) p[o] = 0.f;
#pragma unroll
        for (int q = 0; q < 4; q++) {
            float hv = Cs[row * CS_PITCH + q * 32 + lane];
            const float* w = &sW3[(q * 32 + lane) * EOUT];
#pragma unroll
            for (int o = 0; o < EOUT; o++) p[o] += hv * w[o];
        }
#pragma unroll
        for (int off = 16; off > 0; off >>= 1)
#pragma unroll
            for (int o = 0; o < EOUT; o++)
                p[o] += __shfl_down_sync(0xffffffffu, p[o], off);
        if (lane == 0) {
            float* dst = &g_eo[(size_t)(m0 + row) * (NE * EOUT) + e * EOUT];
#pragma unroll
            for (int o = 0; o < EOUT; o++) dst[o] = p[o] + sEb3[o];
        }
    }
}

// ================= gate + softmax + mmoe + avg + tower (unchanged) ============
__global__ __launch_bounds__(256, 2)
void gate_tower_mma(const float* __restrict__ Gb1,
                    const float* __restrict__ Gw2, const float* __restrict__ Gb2,
                    const float* __restrict__ Tw1, const float* __restrict__ Tb1,
                    const float* __restrict__ Tw2, const float* __restrict__ Tb2,
                    float* __restrict__ out)
{
    extern __shared__ uint32_t sm[];
    float* gh = (float*)sm;
    float* P     = (float*)((char*)sm + 64 * 68 * 4);
    float* sGw2  = P;
    float* sGb2  = P + 384;
    float* sTw1  = P + 392;
    float* sTb1  = P + 1032;
    float* sTw2  = P + 1096;
    float* sGb1  = P + 1160;
    float* sTb2  = P + 1224;
    int*   sIdx  = (int*)(P + 1228);

    const int d    = blockIdx.x;
    const int base = blockIdx.y * 64;
    const int cnt  = g_cnt[d];
    if (base >= cnt) return;
    const int nrows = min(64, cnt - base);

    const int tid = threadIdx.x, lane = tid & 31, wid = tid >> 5;
    const int gid = lane >> 2, tig = lane & 3;
    const int warpM = wid & 3, warpN = wid >> 2;

    if (tid < 64)
        sIdx[tid] = (tid < nrows) ? g_idx[d * BATCH + base + tid]
                                  : g_idx[d * BATCH + base];
    for (int i = tid; i < GHID * NE; i += 256) sGw2[i] = Gw2[d * GHID * NE + i];
    if (tid < NE) sGb2[tid] = Gb2[d * NE + tid];
    for (int i = tid; i < EOUT * THID; i += 256) sTw1[i] = Tw1[d * EOUT * THID + i];
    if (tid < THID) {
        sTb1[tid] = Tb1[d * THID + tid];
        sTw2[tid] = Tw2[d * THID + tid];
        sGb1[tid] = Gb1[d * GHID + tid];
    }
    if (tid == 0) sTb2[0] = Tb2[d];
    __syncthreads();

    const __half* Ap0 = g_xh + (size_t)sIdx[warpM * 16 + gid] * IN_DIM + tig * 8;
    const __half* Ap1 = g_xh + (size_t)sIdx[warpM * 16 + 8 + gid] * IN_DIM + tig * 8;
    const __half* Bp  = g_gw1h + (size_t)(d * GHID + warpN * 32 + gid) * IN_DIM + tig * 8;

    float acc[4][4];
#pragma unroll
    for (int nt = 0; nt < 4; nt++)
#pragma unroll
        for (int q = 0; q < 4; q++) acc[nt][q] = 0.f;

#pragma unroll 2
    for (int c = 0; c < IN_DIM / 32; c++) {
        uint4 A0 = *(const uint4*)(Ap0 + c * 32);
        uint4 A1 = *(const uint4*)(Ap1 + c * 32);
#pragma unroll
        for (int nt = 0; nt < 4; nt++) {
            uint4 Br = *(const uint4*)(Bp + nt * 8 * IN_DIM + c * 32);
            mma16(acc[nt], A0.x, A1.x, A0.y, A1.y, Br.x, Br.y);
            mma16(acc[nt], A0.z, A1.z, A0.w, A1.w, Br.z, Br.w);
        }
    }

#pragma unroll
    for (int nt = 0; nt < 4; nt++) {
        int cc = warpN * 32 + nt * 8 + tig * 2;
        int r0 = warpM * 16 + gid;
        float b0 = sGb1[cc], b1 = sGb1[cc + 1];
        gh[r0 * 68 + cc]           = fmaxf(acc[nt][0] + b0, 0.f);
        gh[r0 * 68 + cc + 1]       = fmaxf(acc[nt][1] + b1, 0.f);
        gh[(r0 + 8) * 68 + cc]     = fmaxf(acc[nt][2] + b0, 0.f);
        gh[(r0 + 8) * 68 + cc + 1] = fmaxf(acc[nt][3] + b1, 0.f);
    }
    __syncthreads();

    if (tid < nrows) {
        const int m = tid;
        const int b = sIdx[m];

        float l[NE];
#pragma unroll
        for (int e = 0; e < NE; e++) l[e] = sGb2[e];
        for (int k = 0; k < GHID; k++) {
            float hv = gh[m * 68 + k];
#pragma unroll
            for (int e = 0; e < NE; e++) l[e] += hv * sGw2[k * NE + e];
        }
        float mx = l[0];
#pragma unroll
        for (int e = 1; e < NE; e++) mx = fmaxf(mx, l[e]);
        float ssum = 0.f;
#pragma unroll
        for (int e = 0; e < NE; e++) { l[e] = expf(l[e] - mx); ssum += l[e]; }
        float inv = 1.f / ssum;

        float mmoe[EOUT], avg[EOUT];
#pragma unroll
        for (int o = 0; o < EOUT; o++) { mmoe[o] = 0.f; avg[o] = 0.f; }
        const float* eorow = g_eo + (size_t)b * (NE * EOUT);
#pragma unroll
        for (int e = 0; e < NE; e++) {
            float gte = l[e] * inv;
#pragma unroll
            for (int o = 0; o < EOUT; o++) {
                float v = eorow[e * EOUT + o];
                mmoe[o] += gte * v;
                avg[o]  += v;
            }
        }
#pragma unroll
        for (int o = 0; o < EOUT; o++) {
            out[BATCH + (size_t)b * EOUT + o]      = avg[o] * (1.f / 6.f);
            out[11 * BATCH + (size_t)b * EOUT + o] = mmoe[o];
        }
        float tacc = sTb2[0];
        for (int h = 0; h < THID; h++) {
            float th = sTb1[h];
#pragma unroll
            for (int o = 0; o < EOUT; o++) th += mmoe[o] * sTw1[o * THID + h];
            th = fmaxf(th, 0.f);
            tacc += th * sTw2[h];
        }
        out[b] = 1.f / (1.f + expf(-tacc));
    }
}

// ------------------------------------------------------------------
extern "C" void kernel_launch(void* const* d_in, const int* in_sizes, int n_in,
                              void* d_out, int out_size)
{
    const float* x    = (const float*)d_in[0];
    const int*   dom  = (const int*)d_in[1];
    const float* Ew1  = (const float*)d_in[2];
    const float* Eb1  = (const float*)d_in[3];
    const float* Ew2  = (const float*)d_in[4];
    const float* Eb2  = (const float*)d_in[5];
    const float* Ew3  = (const float*)d_in[6];
    const float* Eb3  = (const float*)d_in[7];
    const float* Gw1  = (const float*)d_in[8];
    const float* Gb1  = (const float*)d_in[9];
    const float* Gw2  = (const float*)d_in[10];
    const float* Gb2  = (const float*)d_in[11];
    const float* Tw1  = (const float*)d_in[12];
    const float* Tb1  = (const float*)d_in[13];
    const float* Tw2  = (const float*)d_in[14];
    const float* Tb2  = (const float*)d_in[15];
    float* out = (float*)d_out;

    __half* w1h = nullptr; __half* w2h = nullptr; __half* gw1h = nullptr;
    cudaGetSymbolAddress((void**)&w1h,  g_w1h);
    cudaGetSymbolAddress((void**)&w2h,  g_w2h);
    cudaGetSymbolAddress((void**)&gw1h, g_gw1h);

    const int SMEM2 = 128 * CS_PITCH * 4 + (H2D * EOUT + 16) * 4;
    const int SMEMG = 64 * 68 * 4 + 1292 * 4 + 256;
    cudaFuncSetAttribute(expert_l2_mma, cudaFuncAttributeMaxDynamicSharedMemorySize, SMEM2);
    cudaFuncSetAttribute(gate_tower_mma, cudaFuncAttributeMaxDynamicSharedMemorySize, SMEMG);

    // expert_l1_mma at index 3 (the ncu-captured slot)
    x_prep_kernel<<<(BATCH * IN_DIM / 8) / 256, 256>>>(x);
    w_prep_all_kernel<<<3008, dim3(32, 8)>>>(Ew1, Ew2, Gw1, w1h, w2h, gw1h);
    bucket_kernel<<<(BATCH + 255) / 256, 256>>>(dom);
    expert_l1_mma<<<dim3(BATCH / 256, 2, NE), 256>>>(Eb1);
    expert_l2_mma<<<dim3(BATCH / 128, 1, NE), 256, SMEM2>>>(Eb2, Ew3, Eb3);
    gate_tower_mma<<<dim3(ND, (BATCH + 63) / 64), 256, SMEMG>>>(
        Gb1, Gw2, Gb2, Tw1, Tb1, Tw2, Tb2, out);

    (void)in_sizes; (void)n_in; (void)out_size;
}

// round 14
// speedup vs baseline: 1.1568x; 1.1568x over previous
#include <cuda_runtime.h>
#include <cuda_fp16.h>
#include <cstdint>
#include <math.h>

#define BATCH   16384
#define IN_DIM  1024
#define NE      6
#define ND      20
#define H1D     256
#define H2D     128
#define EOUT    10
#define GHID    64
#define THID    64

// ---- scratch (device globals; no allocations allowed) ----
// g_xh, g_w1h: FRAGMENT-PACKED fp16: frag = [8 rows x 32 k] = 512B contiguous.
//   X:  frag id f = (m/8)*32 + kChunk; offset within = (m%8)*32 + perm16(k)
//   W1: frag id f = e*(H1D/8)*32 + (n/8)*32 + kChunk
// g_w2h, g_gw1h, g_h1h: row-major k-permuted (R12 layout).
__device__ __half g_xh[BATCH * IN_DIM];        // packed      (32 MB)
__device__ __half g_w1h[NE * H1D * IN_DIM];    // packed      (3 MB)
__device__ __half g_w2h[NE * H2D * H1D];       // row k-perm  (384 KB)
__device__ __half g_gw1h[ND * GHID * IN_DIM];  // row k-perm  (2.6 MB)
__device__ __half g_h1h[BATCH * NE * H1D];     // row k-perm  (50 MB)
__device__ float  g_eo[BATCH * NE * EOUT];     // fp32        (3.9 MB)
__device__ int    g_cnt[ND];
__device__ int    g_idx[ND * BATCH];

// ================= helpers =================
__device__ __forceinline__ uint32_t h2_as_u32(__half2 h) {
    return *(uint32_t*)&h;
}
__device__ __host__ __forceinline__ int perm16(int k) {
    return ((k & 7) >> 1) * 8 + (k >> 3) * 2 + (k & 1);
}
__device__ __forceinline__ void mma16(float* c,
                                      uint32_t a0, uint32_t a1, uint32_t a2, uint32_t a3,
                                      uint32_t b0, uint32_t b1) {
    asm volatile(
        "mma.sync.aligned.m16n8k16.row.col.f32.f16.f16.f32 "
        "{%0,%1,%2,%3}, {%4,%5,%6,%7}, {%8,%9}, {%0,%1,%2,%3};"
        : "+f"(c[0]), "+f"(c[1]), "+f"(c[2]), "+f"(c[3])
        : "r"(a0), "r"(a1), "r"(a2), "r"(a3), "r"(b0), "r"(b1));
}

// ================= prep: X -> fragment-packed fp16 + zero counters =============
// warp-per-fragment: warp w handles frag f; lane (r=lane>>2, t=lane&3)
// reads row mb*8+r, k-window c*32 + {2t,2t+1,8+2t,...}; stores 16B at r*32+t*8.
__global__ void x_prep_kernel(const float* __restrict__ X) {
    if (blockIdx.x == 0 && threadIdx.x < ND) g_cnt[threadIdx.x] = 0;
    int idx = blockIdx.x * 256 + threadIdx.x;        // 2M threads
    int f = idx >> 5;                                // fragment id
    int lane = idx & 31;
    int r = lane >> 2, t = lane & 3;
    int mb = f >> 5, c = f & 31;
    int m = mb * 8 + r;
    const float* src = X + (size_t)m * IN_DIM + c * 32 + 2 * t;
    float2 v0 = *(const float2*)(src + 0);
    float2 v1 = *(const float2*)(src + 8);
    float2 v2 = *(const float2*)(src + 16);
    float2 v3 = *(const float2*)(src + 24);
    uint4 o;
    o.x = h2_as_u32(__floats2half2_rn(v0.x, v0.y));
    o.y = h2_as_u32(__floats2half2_rn(v1.x, v1.y));
    o.z = h2_as_u32(__floats2half2_rn(v2.x, v2.y));
    o.w = h2_as_u32(__floats2half2_rn(v3.x, v3.y));
    *(uint4*)(g_xh + (size_t)f * 256 + r * 32 + t * 8) = o;
}

// ================= bucketing =================
__global__ void bucket_kernel(const int* __restrict__ dom) {
    int b = blockIdx.x * blockDim.x + threadIdx.x;
    if (b < BATCH) {
        int d = dom[b];
        int p = atomicAdd(&g_cnt[d], 1);
        g_idx[d * BATCH + p] = b;
    }
}

// ================= merged weight prep =================
// packed=true -> fragment-packed store; false -> row-major k-perm (R12)
template<bool PACKED>
__device__ __forceinline__ void w_prep_tile(const float* __restrict__ W,
                                            __half* __restrict__ WT,
                                            int K, int N, int e, int kbi, int nbi,
                                            float (*tile)[33])
{
    int k0 = kbi * 32, n0 = nbi * 32;
    const float* Wp = W + (size_t)e * K * N;
    __half* Tp = WT + (size_t)e * N * K;
    int tx = threadIdx.x, ty = threadIdx.y;
#pragma unroll
    for (int j = 0; j < 32; j += 8)
        tile[ty + j][tx] = Wp[(size_t)(k0 + ty + j) * N + n0 + tx];
    __syncthreads();
#pragma unroll
    for (int j = 0; j < 32; j += 8) {
        int n = n0 + ty + j;
        __half v = __float2half_rn(tile[tx][ty + j]);
        if (PACKED) {
            size_t off = ((size_t)(n >> 3) * (K / 32) + kbi) * 256
                       + (n & 7) * 32 + perm16(tx);
            Tp[off] = v;
        } else {
            Tp[(size_t)n * K + k0 + perm16(tx)] = v;
        }
    }
}

__global__ void w_prep_all_kernel(const float* __restrict__ Ew1,
                                  const float* __restrict__ Ew2,
                                  const float* __restrict__ Gw1,
                                  __half* __restrict__ w1h,
                                  __half* __restrict__ w2h,
                                  __half* __restrict__ gw1h)
{
    __shared__ float tile[32][33];
    int b = blockIdx.x;
    if (b < 1536) {
        int e = b >> 8, r = b & 255;
        w_prep_tile<true>(Ew1, w1h, IN_DIM, H1D, e, r & 31, r >> 5, tile);   // packed
    } else if (b < 1728) {
        int bb = b - 1536;
        int e = bb >> 5, r = bb & 31;
        w_prep_tile<false>(Ew2, w2h, H1D, H2D, e, r & 7, r >> 3, tile);
    } else {
        int bb = b - 1728;
        int d = bb >> 6, r = bb & 63;
        w_prep_tile<false>(Gw1, gw1h, IN_DIM, GHID, d, r & 31, r >> 5, tile);
    }
}

// ================= expert L1: 128x128 tile, packed-fragment LDG =================
// grid (128, 2, 6); 2 CTA/SM
__global__ __launch_bounds__(256, 2)
void expert_l1_mma(const float* __restrict__ bias)
{
    const int tid = threadIdx.x, lane = tid & 31, wid = tid >> 5;
    const int gid = lane >> 2, tig = lane & 3;
    const int warpM = wid & 3, warpN = wid >> 2;
    const int m0 = blockIdx.x * 128;
    const int n0 = blockIdx.y * 128;
    const int e  = blockIdx.z;
    const int toff = gid * 32 + tig * 8;

    // A frags: mb = m0/8 + warpM*4 + (mt*2+rr); 32 chunks each
    const __half* Apf[2][2];
#pragma unroll
    for (int mt = 0; mt < 2; mt++)
#pragma unroll
        for (int rr = 0; rr < 2; rr++)
            Apf[mt][rr] = g_xh + (size_t)(m0 / 8 + warpM * 4 + mt * 2 + rr) * 32 * 256 + toff;
    // B frags: fb = e*(H1D/8) + n0/8 + warpN*8 + nt; 32 chunks each
    const __half* Bpf = g_w1h
        + (size_t)(e * (H1D / 8) + n0 / 8 + warpN * 8) * 32 * 256 + toff;

    float acc[2][8][4];
#pragma unroll
    for (int mt = 0; mt < 2; mt++)
#pragma unroll
        for (int nt = 0; nt < 8; nt++)
#pragma unroll
            for (int q = 0; q < 4; q++) acc[mt][nt][q] = 0.f;

#pragma unroll 2
    for (int c = 0; c < IN_DIM / 32; c++) {
        uint4 Ar[2][2];
#pragma unroll
        for (int mt = 0; mt < 2; mt++)
#pragma unroll
            for (int rr = 0; rr < 2; rr++)
                Ar[mt][rr] = *(const uint4*)(Apf[mt][rr] + c * 256);
#pragma unroll
        for (int nt = 0; nt < 8; nt++) {
            uint4 Br = *(const uint4*)(Bpf + ((size_t)nt * 32 + c) * 256);
#pragma unroll
            for (int mt = 0; mt < 2; mt++) {
                mma16(acc[mt][nt], Ar[mt][0].x, Ar[mt][1].x, Ar[mt][0].y, Ar[mt][1].y, Br.x, Br.y);
                mma16(acc[mt][nt], Ar[mt][0].z, Ar[mt][1].z, Ar[mt][0].w, Ar[mt][1].w, Br.z, Br.w);
            }
        }
    }

    // epilogue: bias + relu -> R12 h1 layout (row-major k-perm); STG.128
#pragma unroll
    for (int mt = 0; mt < 2; mt++)
#pragma unroll
        for (int rr = 0; rr < 2; rr++) {
            int row = m0 + warpM * 32 + mt * 16 + rr * 8 + gid;
#pragma unroll
            for (int cc = 0; cc < 2; cc++) {
                uint32_t v[4];
#pragma unroll
                for (int q = 0; q < 4; q++) {
                    int nt = cc * 4 + q;
                    int nn = n0 + warpN * 64 + nt * 8 + tig * 2;
                    float b0 = bias[e * H1D + nn];
                    float b1 = bias[e * H1D + nn + 1];
                    v[q] = h2_as_u32(__floats2half2_rn(
                        fmaxf(acc[mt][nt][rr * 2 + 0] + b0, 0.f),
                        fmaxf(acc[mt][nt][rr * 2 + 1] + b1, 0.f)));
                }
                char* dst = (char*)g_h1h + (size_t)row * (NE * H1D * 2) + e * (H1D * 2)
                          + (size_t)(n0 / 32 + warpN * 2 + cc) * 64 + tig * 16;
                *(uint4*)dst = make_uint4(v[0], v[1], v[2], v[3]);
            }
        }
}

// ================= expert L2 (+fused L3): unchanged from R12 =================
#define CS_PITCH 132
__global__ __launch_bounds__(256, 2)
void expert_l2_mma(const float* __restrict__ b2, const float* __restrict__ W3,
                   const float* __restrict__ b3)
{
    extern __shared__ uint32_t sm[];
    float* Cs   = (float*)sm;
    float* sW3  = (float*)((char*)sm + 128 * CS_PITCH * 4);
    float* sEb3 = sW3 + H2D * EOUT;

    const int tid = threadIdx.x, lane = tid & 31, wid = tid >> 5;
    const int gid = lane >> 2, tig = lane & 3;
    const int warpM = wid & 3, warpN = wid >> 2;
    const int m0 = blockIdx.x * 128;
    const int e  = blockIdx.z;

    for (int i = tid; i < H2D * EOUT; i += 256) sW3[i] = W3[e * H2D * EOUT + i];
    if (tid < EOUT) sEb3[tid] = b3[e * EOUT + tid];

    const __half* Ap = g_h1h + (size_t)(m0 + warpM * 32 + gid) * (NE * H1D) + e * H1D + tig * 8;
    const __half* Bp = g_w2h + (size_t)(e * H2D + warpN * 64 + gid) * H1D + tig * 8;

    float acc[2][8][4];
#pragma unroll
    for (int mt = 0; mt < 2; mt++)
#pragma unroll
        for (int nt = 0; nt < 8; nt++)
#pragma unroll
            for (int q = 0; q < 4; q++) acc[mt][nt][q] = 0.f;

#pragma unroll
    for (int c = 0; c < H1D / 32; c++) {
        const __half* Ac = Ap + c * 32;
        const __half* Bc = Bp + c * 32;
        uint4 Ar[2][2];
#pragma unroll
        for (int mt = 0; mt < 2; mt++)
#pragma unroll
            for (int rr = 0; rr < 2; rr++)
                Ar[mt][rr] = *(const uint4*)(Ac + (mt * 16 + rr * 8) * (NE * H1D));
#pragma unroll
        for (int nt = 0; nt < 8; nt++) {
            uint4 Br = *(const uint4*)(Bc + nt * 8 * H1D);
#pragma unroll
            for (int mt = 0; mt < 2; mt++) {
                mma16(acc[mt][nt], Ar[mt][0].x, Ar[mt][1].x, Ar[mt][0].y, Ar[mt][1].y, Br.x, Br.y);
                mma16(acc[mt][nt], Ar[mt][0].z, Ar[mt][1].z, Ar[mt][0].w, Ar[mt][1].w, Br.z, Br.w);
            }
        }
    }

    __syncthreads();
#pragma unroll
    for (int mt = 0; mt < 2; mt++) {
        int r = warpM * 32 + mt * 16 + gid;
#pragma unroll
        for (int nt = 0; nt < 8; nt++) {
            int cc = warpN * 64 + nt * 8 + tig * 2;
            float bb0 = b2[e * H2D + cc];
            float bb1 = b2[e * H2D + cc + 1];
            Cs[r * CS_PITCH + cc]           = fmaxf(acc[mt][nt][0] + bb0, 0.f);
            Cs[r * CS_PITCH + cc + 1]       = fmaxf(acc[mt][nt][1] + bb1, 0.f);
            Cs[(r + 8) * CS_PITCH + cc]     = fmaxf(acc[mt][nt][2] + bb0, 0.f);
            Cs[(r + 8) * CS_PITCH + cc + 1] = fmaxf(acc[mt][nt][3] + bb1, 0.f);
        }
    }
    __syncthreads();

    for (int rr = 0; rr < 16; rr++) {
        int row = wid * 16 + rr;
        float p[EOUT];
#pragma unroll
        for (int o = 0; o < EOUT; o++) p[o] = 0.f;
#pragma unroll
        for (int q = 0; q < 4; q++) {
            float hv = Cs[row * CS_PITCH + q * 32 + lane];
            const float* w = &sW3[(q * 32 + lane) * EOUT];
#pragma unroll
            for (int o = 0; o < EOUT; o++) p[o] += hv * w[o];
        }
#pragma unroll
        for (int off = 16; off > 0; off >>= 1)
#pragma unroll
            for (int o = 0; o < EOUT; o++)
                p[o] += __shfl_down_sync(0xffffffffu, p[o], off);
        if (lane == 0) {
            float* dst = &g_eo[(size_t)(m0 + row) * (NE * EOUT) + e * EOUT];
#pragma unroll
            for (int o = 0; o < EOUT; o++) dst[o] = p[o] + sEb3[o];
        }
    }
}

// ================= gate + softmax + mmoe + avg + tower (packed-X gather) =======
__global__ __launch_bounds__(256, 2)
void gate_tower_mma(const float* __restrict__ Gb1,
                    const float* __restrict__ Gw2, const float* __restrict__ Gb2,
                    const float* __restrict__ Tw1, const float* __restrict__ Tb1,
                    const float* __restrict__ Tw2, const float* __restrict__ Tb2,
                    float* __restrict__ out)
{
    extern __shared__ uint32_t sm[];
    float* gh = (float*)sm;
    float* P     = (float*)((char*)sm + 64 * 68 * 4);
    float* sGw2  = P;
    float* sGb2  = P + 384;
    float* sTw1  = P + 392;
    float* sTb1  = P + 1032;
    float* sTw2  = P + 1096;
    float* sGb1  = P + 1160;
    float* sTb2  = P + 1224;
    int*   sIdx  = (int*)(P + 1228);

    const int d    = blockIdx.x;
    const int base = blockIdx.y * 64;
    const int cnt  = g_cnt[d];
    if (base >= cnt) return;
    const int nrows = min(64, cnt - base);

    const int tid = threadIdx.x, lane = tid & 31, wid = tid >> 5;
    const int gid = lane >> 2, tig = lane & 3;
    const int warpM = wid & 3, warpN = wid >> 2;

    if (tid < 64)
        sIdx[tid] = (tid < nrows) ? g_idx[d * BATCH + base + tid]
                                  : g_idx[d * BATCH + base];
    for (int i = tid; i < GHID * NE; i += 256) sGw2[i] = Gw2[d * GHID * NE + i];
    if (tid < NE) sGb2[tid] = Gb2[d * NE + tid];
    for (int i = tid; i < EOUT * THID; i += 256) sTw1[i] = Tw1[d * EOUT * THID + i];
    if (tid < THID) {
        sTb1[tid] = Tb1[d * THID + tid];
        sTw2[tid] = Tw2[d * THID + tid];
        sGb1[tid] = Gb1[d * GHID + tid];
    }
    if (tid == 0) sTb2[0] = Tb2[d];
    __syncthreads();

    // packed-X gather: row m lives at frag (m>>3)*32 + c, inner (m&7)*32 + tig*8
    const int mA0 = sIdx[warpM * 16 + gid];
    const int mA1 = sIdx[warpM * 16 + 8 + gid];
    const __half* Ap0 = g_xh + (size_t)(mA0 >> 3) * 32 * 256 + (mA0 & 7) * 32 + tig * 8;
    const __half* Ap1 = g_xh + (size_t)(mA1 >> 3) * 32 * 256 + (mA1 & 7) * 32 + tig * 8;
    const __half* Bp  = g_gw1h + (size_t)(d * GHID + warpN * 32 + gid) * IN_DIM + tig * 8;

    float acc[4][4];
#pragma unroll
    for (int nt = 0; nt < 4; nt++)
#pragma unroll
        for (int q = 0; q < 4; q++) acc[nt][q] = 0.f;

#pragma unroll 2
    for (int c = 0; c < IN_DIM / 32; c++) {
        uint4 A0 = *(const uint4*)(Ap0 + c * 256);
        uint4 A1 = *(const uint4*)(Ap1 + c * 256);
#pragma unroll
        for (int nt = 0; nt < 4; nt++) {
            uint4 Br = *(const uint4*)(Bp + nt * 8 * IN_DIM + c * 32);
            mma16(acc[nt], A0.x, A1.x, A0.y, A1.y, Br.x, Br.y);
            mma16(acc[nt], A0.z, A1.z, A0.w, A1.w, Br.z, Br.w);
        }
    }

#pragma unroll
    for (int nt = 0; nt < 4; nt++) {
        int cc = warpN * 32 + nt * 8 + tig * 2;
        int r0 = warpM * 16 + gid;
        float b0 = sGb1[cc], b1 = sGb1[cc + 1];
        gh[r0 * 68 + cc]           = fmaxf(acc[nt][0] + b0, 0.f);
        gh[r0 * 68 + cc + 1]       = fmaxf(acc[nt][1] + b1, 0.f);
        gh[(r0 + 8) * 68 + cc]     = fmaxf(acc[nt][2] + b0, 0.f);
        gh[(r0 + 8) * 68 + cc + 1] = fmaxf(acc[nt][3] + b1, 0.f);
    }
    __syncthreads();

    if (tid < nrows) {
        const int m = tid;
        const int b = sIdx[m];

        float l[NE];
#pragma unroll
        for (int e = 0; e < NE; e++) l[e] = sGb2[e];
        for (int k = 0; k < GHID; k++) {
            float hv = gh[m * 68 + k];
#pragma unroll
            for (int e = 0; e < NE; e++) l[e] += hv * sGw2[k * NE + e];
        }
        float mx = l[0];
#pragma unroll
        for (int e = 1; e < NE; e++) mx = fmaxf(mx, l[e]);
        float ssum = 0.f;
#pragma unroll
        for (int e = 0; e < NE; e++) { l[e] = expf(l[e] - mx); ssum += l[e]; }
        float inv = 1.f / ssum;

        float mmoe[EOUT], avg[EOUT];
#pragma unroll
        for (int o = 0; o < EOUT; o++) { mmoe[o] = 0.f; avg[o] = 0.f; }
        const float* eorow = g_eo + (size_t)b * (NE * EOUT);
#pragma unroll
        for (int e = 0; e < NE; e++) {
            float gte = l[e] * inv;
#pragma unroll
            for (int o = 0; o < EOUT; o++) {
                float v = eorow[e * EOUT + o];
                mmoe[o] += gte * v;
                avg[o]  += v;
            }
        }
#pragma unroll
        for (int o = 0; o < EOUT; o++) {
            out[BATCH + (size_t)b * EOUT + o]      = avg[o] * (1.f / 6.f);
            out[11 * BATCH + (size_t)b * EOUT + o] = mmoe[o];
        }
        float tacc = sTb2[0];
        for (int h = 0; h < THID; h++) {
            float th = sTb1[h];
#pragma unroll
            for (int o = 0; o < EOUT; o++) th += mmoe[o] * sTw1[o * THID + h];
            th = fmaxf(th, 0.f);
            tacc += th * sTw2[h];
        }
        out[b] = 1.f / (1.f + expf(-tacc));
    }
}

// ------------------------------------------------------------------
extern "C" void kernel_launch(void* const* d_in, const int* in_sizes, int n_in,
                              void* d_out, int out_size)
{
    const float* x    = (const float*)d_in[0];
    const int*   dom  = (const int*)d_in[1];
    const float* Ew1  = (const float*)d_in[2];
    const float* Eb1  = (const float*)d_in[3];
    const float* Ew2  = (const float*)d_in[4];
    const float* Eb2  = (const float*)d_in[5];
    const float* Ew3  = (const float*)d_in[6];
    const float* Eb3  = (const float*)d_in[7];
    const float* Gw1  = (const float*)d_in[8];
    const float* Gb1  = (const float*)d_in[9];
    const float* Gw2  = (const float*)d_in[10];
    const float* Gb2  = (const float*)d_in[11];
    const float* Tw1  = (const float*)d_in[12];
    const float* Tb1  = (const float*)d_in[13];
    const float* Tw2  = (const float*)d_in[14];
    const float* Tb2  = (const float*)d_in[15];
    float* out = (float*)d_out;

    __half* w1h = nullptr; __half* w2h = nullptr; __half* gw1h = nullptr;
    cudaGetSymbolAddress((void**)&w1h,  g_w1h);
    cudaGetSymbolAddress((void**)&w2h,  g_w2h);
    cudaGetSymbolAddress((void**)&gw1h, g_gw1h);

    const int SMEM2 = 128 * CS_PITCH * 4 + (H2D * EOUT + 16) * 4;
    const int SMEMG = 64 * 68 * 4 + 1292 * 4 + 256;
    cudaFuncSetAttribute(expert_l2_mma, cudaFuncAttributeMaxDynamicSharedMemorySize, SMEM2);
    cudaFuncSetAttribute(gate_tower_mma, cudaFuncAttributeMaxDynamicSharedMemorySize, SMEMG);

    // expert_l1_mma at index 3 (the ncu-captured slot)
    x_prep_kernel<<<(BATCH * IN_DIM / 8) / 256, 256>>>(x);
    w_prep_all_kernel<<<3008, dim3(32, 8)>>>(Ew1, Ew2, Gw1, w1h, w2h, gw1h);
    bucket_kernel<<<(BATCH + 255) / 256, 256>>>(dom);
    expert_l1_mma<<<dim3(BATCH / 128, 2, NE), 256>>>(Eb1);
    expert_l2_mma<<<dim3(BATCH / 128, 1, NE), 256, SMEM2>>>(Eb2, Ew3, Eb3);
    gate_tower_mma<<<dim3(ND, (BATCH + 63) / 64), 256, SMEMG>>>(
        Gb1, Gw2, Gb2, Tw1, Tb1, Tw2, Tb2, out);

    (void)in_sizes; (void)n_in; (void)out_size;
}